// round 14
// baseline (speedup 1.0000x reference)
#include <cuda_runtime.h>
#include <cstdint>

// VQ quantize: hh-only tf32 MMA prefilter (1/3 FLOPs) + provably-sufficient
// candidate rescore with the bit-exact R1 scalar formula (known-pass argmin).
// x: [131072, 64] f32, embed: [64, 512] f32.
// Out f32: quantize (8388608) | diff (1) | embed_ind (131072).

#define DIMK 64
#define NCODE 512
#define NROWS (32 * 64 * 64)
#define NTOT (NROWS * DIMK)
#define TPB 256
#define M_TILE 128
#define NBLK (NROWS / M_TILE)   // 1024

// quantization of prefilter scores (conservative, floor/ceil handled)
#define QOFF 512.0f
#define QINVS 0.25f

// smem layout (bytes)
#define SM_BH0 0                 // 16384  (8 nc-blocks of hh B fragments)
#define SM_BH1 16384             // 16384
#define SM_NRM 32768             // 2048   float[512]
#define SM_BLKMIN 34816          // 8192   u8[128][64]
#define SM_QTHR 43008            // 512    int[128]
#define SM_CLIST 43520           // 4096   u32[1024]
#define SM_CCNT 47616            // 16
#define SM_ROWBEST 47632         // 1024   ull[128]
#define SM_WIN 48656             // 512    int[128]
#define SM_RED 49168             // 1024   float[256]
#define SM_BYTES 50192

typedef unsigned long long ull;

__device__ __align__(16) float2 g_Bh[64 * 8 * 32];     // [nc][kc][lane] = {bh0,bh1}
__device__ __align__(16) float g_embT[NCODE * DIMK];   // fp32 codes [k][d]
__device__ float g_nrm[NCODE];
__device__ float g_maxE2;                              // max ||e||^2 (atomicMax)
__device__ unsigned long long g_diff_acc;
__device__ unsigned int g_ticket;

__device__ __forceinline__ uint32_t smem_u32(const void* p) {
    uint32_t a;
    asm("{ .reg .u64 t; cvta.to.shared.u64 t, %1; cvt.u32.u64 %0, t; }" : "=r"(a) : "l"(p));
    return a;
}
__device__ __forceinline__ uint32_t tf32_hi(float f) {
    uint32_t r;
    asm("cvt.rna.tf32.f32 %0, %1;" : "=r"(r) : "f"(f));
    return r;
}
__device__ __forceinline__ void mma8(float* c, const uint32_t* a, uint32_t b0, uint32_t b1) {
    asm("mma.sync.aligned.m16n8k8.row.col.f32.tf32.tf32.f32 "
        "{%0,%1,%2,%3}, {%4,%5,%6,%7}, {%8,%9}, {%0,%1,%2,%3};"
        : "+f"(c[0]), "+f"(c[1]), "+f"(c[2]), "+f"(c[3])
        : "r"(a[0]), "r"(a[1]), "r"(a[2]), "r"(a[3]), "r"(b0), "r"(b1));
}
__device__ __forceinline__ void cp16(uint32_t s, const void* g) {
    asm volatile("cp.async.cg.shared.global [%0], [%1], 16;" :: "r"(s), "l"(g) : "memory");
}
#define CP_COMMIT() asm volatile("cp.async.commit_group;" ::: "memory")
#define CP_WAIT1()  asm volatile("cp.async.wait_group 1;" ::: "memory")
#define CP_WAIT0()  asm volatile("cp.async.wait_group 0;" ::: "memory")

__device__ __forceinline__ uint32_t fkey(float f) {
    uint32_t b = __float_as_uint(f);
    return (b & 0x80000000u) ? ~b : (b | 0x80000000u);
}

// ---- prep: codebook transpose, norms (R1-exact chain), maxE^2, hh B frags ----
__global__ void vq_prep(const float* __restrict__ embed) {
    int gtid = blockIdx.x * blockDim.x + threadIdx.x;   // 16384

    if (gtid < NCODE) {
        int t = gtid;
        float nr = 0.f;
        for (int d = 0; d < DIMK; d++) {
            float e = embed[d * NCODE + t];
            g_embT[t * DIMK + d] = e;
            nr = fmaf(e, e, nr);
        }
        g_nrm[t] = nr;
        atomicMax((int*)&g_maxE2, __float_as_int(nr));  // nr >= 0: int-bit compare ok
    }

    int i = gtid;   // [nc][kc][lane]
    int lane = i & 31;
    int kc = (i >> 5) & 7;
    int nc = i >> 8;
    int gid = lane >> 2, tig = lane & 3;
    int n = nc * 8 + gid;
    int k0 = kc * 8 + tig;
    float v0 = -2.f * embed[k0 * NCODE + n];
    float v1 = -2.f * embed[(k0 + 4) * NCODE + n];
    float2 f;
    f.x = __uint_as_float(tf32_hi(v0));
    f.y = __uint_as_float(tf32_hi(v1));
    g_Bh[i] = f;
}

__global__ __launch_bounds__(TPB, 3)
void vq_mma_kernel(const float* __restrict__ x,
                   float* __restrict__ out,
                   int out_size) {
    extern __shared__ char smem[];
    float* nsm = (float*)(smem + SM_NRM);
    unsigned char* BLKMIN = (unsigned char*)(smem + SM_BLKMIN);
    int* QTHR = (int*)(smem + SM_QTHR);
    uint32_t* CLIST = (uint32_t*)(smem + SM_CLIST);
    int* CCNT = (int*)(smem + SM_CCNT);
    ull* ROWBEST = (ull*)(smem + SM_ROWBEST);
    int* WIN = (int*)(smem + SM_WIN);
    float* red = (float*)(smem + SM_RED);

    int tid = threadIdx.x, wid = tid >> 5, lane = tid & 31;
    int gid = lane >> 2, tig = lane & 3;
    int base_row = blockIdx.x * M_TILE;
    const uint32_t FULL = 0xffffffffu;

    if (tid == 0) CCNT[0] = 0;
    for (int i = tid; i < 128; i += TPB) ROWBEST[i] = ~0ull;

    // async load of Bh chunk 0 (16KB = 1024 uint4)
    {
        uint32_t dst = smem_u32(smem + SM_BH0) + tid * 16;
        const uint4* src = ((const uint4*)g_Bh) + tid;
#pragma unroll
        for (int i = 0; i < 1024 / TPB; i++)
            cp16(dst + i * TPB * 16, src + i * TPB);
        CP_COMMIT();
    }

    for (int i = tid; i < NCODE; i += TPB) nsm[i] = g_nrm[i];

    // A fragments (tf32 hi only) + per-row ||x||^2 partials
    int m0 = wid * 16;
    uint32_t Ah[8][4];
    float nx0 = 0.f, nx1 = 0.f;
    {
        const float* xr0 = x + (size_t)(base_row + m0 + gid) * DIMK;
        const float* xr8 = xr0 + 8 * DIMK;
#pragma unroll
        for (int kc = 0; kc < 8; kc++) {
            int c0 = kc * 8 + tig;
            float f0 = __ldg(xr0 + c0);
            float f1 = __ldg(xr8 + c0);
            float f2 = __ldg(xr0 + c0 + 4);
            float f3 = __ldg(xr8 + c0 + 4);
            Ah[kc][0] = tf32_hi(f0);
            Ah[kc][1] = tf32_hi(f1);
            Ah[kc][2] = tf32_hi(f2);
            Ah[kc][3] = tf32_hi(f3);
            nx0 = fmaf(f0, f0, nx0); nx0 = fmaf(f2, f2, nx0);
            nx1 = fmaf(f1, f1, nx1); nx1 = fmaf(f3, f3, nx1);
        }
    }
    nx0 += __shfl_xor_sync(FULL, nx0, 1); nx0 += __shfl_xor_sync(FULL, nx0, 2);
    nx1 += __shfl_xor_sync(FULL, nx1, 1); nx1 += __shfl_xor_sync(FULL, nx1, 2);

    float best0 = __int_as_float(0x7f800000), best1 = best0;

    // ---- pass 1: hh-only MMA over 8 chunks x 8 blocks ----
#pragma unroll 1
    for (int c = 0; c < 8; c++) {
        if (c < 7) {
            uint32_t dst = smem_u32(smem + ((c & 1) ? SM_BH0 : SM_BH1)) + tid * 16;
            const uint4* src = ((const uint4*)g_Bh) + (c + 1) * 1024 + tid;
#pragma unroll
            for (int i = 0; i < 1024 / TPB; i++)
                cp16(dst + i * TPB * 16, src + i * TPB);
            CP_COMMIT();
            CP_WAIT1();
        } else {
            CP_WAIT0();
        }
        __syncthreads();

        const float2* Bq = (const float2*)(smem + ((c & 1) ? SM_BH1 : SM_BH0));

#pragma unroll 2
        for (int ncl = 0; ncl < 8; ncl++) {
            float2 b[8];
#pragma unroll
            for (int kc = 0; kc < 8; kc++) b[kc] = Bq[(ncl * 8 + kc) * 32 + lane];

            float hh[4] = {0, 0, 0, 0};
#pragma unroll
            for (int kc = 0; kc < 8; kc++)
                mma8(hh, Ah[kc], __float_as_uint(b[kc].x), __float_as_uint(b[kc].y));

            int blk = c * 8 + ncl;
            float2 nv = *(const float2*)(nsm + blk * 8 + 2 * tig);
            float s0 = hh[0] + nv.x, s1 = hh[1] + nv.y;
            float s2 = hh[2] + nv.x, s3 = hh[3] + nv.y;
            float bm0 = fminf(s0, s1), bm1 = fminf(s2, s3);
            best0 = fminf(best0, bm0);
            best1 = fminf(best1, bm1);
            bm0 = fminf(bm0, __shfl_xor_sync(FULL, bm0, 1));
            bm0 = fminf(bm0, __shfl_xor_sync(FULL, bm0, 2));
            bm1 = fminf(bm1, __shfl_xor_sync(FULL, bm1, 1));
            bm1 = fminf(bm1, __shfl_xor_sync(FULL, bm1, 2));
            if (tig == 0) {
                int q0 = (int)floorf((bm0 + QOFF) * QINVS);
                int q1 = (int)floorf((bm1 + QOFF) * QINVS);
                q0 = max(0, min(255, q0));
                q1 = max(0, min(255, q1));
                BLKMIN[(m0 + gid) * 64 + blk] = (unsigned char)q0;
                BLKMIN[(m0 + gid + 8) * 64 + blk] = (unsigned char)q1;
            }
        }
        __syncthreads();
    }

    // ---- row mins + conservative thresholds ----
    best0 = fminf(best0, __shfl_xor_sync(FULL, best0, 1));
    best0 = fminf(best0, __shfl_xor_sync(FULL, best0, 2));
    best1 = fminf(best1, __shfl_xor_sync(FULL, best1, 1));
    best1 = fminf(best1, __shfl_xor_sync(FULL, best1, 2));
    {
        float maxE = sqrtf(__ldg(&g_maxE2));
        if (tig == 0) {
            float B0 = 0.00390625f * sqrtf(nx0) * maxE + 0.05f;   // 2^-8*||x||*maxE + slack
            float B1 = 0.00390625f * sqrtf(nx1) * maxE + 0.05f;
            float thr0 = best0 + 2.f * B0;
            float thr1 = best1 + 2.f * B1;
            int q0 = (int)ceilf((thr0 + QOFF) * QINVS);
            int q1 = (int)ceilf((thr1 + QOFF) * QINVS);
            QTHR[m0 + gid] = max(0, min(255, q0));
            QTHR[m0 + gid + 8] = max(0, min(255, q1));
        }
    }
    __syncthreads();

    // ---- scan BLKMIN, push flagged (row, block) ----
    {
        int row = tid >> 1;                       // 2 threads per row
        int w0 = (tid & 1) * 8;                   // 8 u32 words each (half row)
        int qt = QTHR[row];
        const uint32_t* bm32 = (const uint32_t*)(BLKMIN + row * 64);
#pragma unroll
        for (int w = 0; w < 8; w++) {
            uint32_t v = bm32[w0 + w];
#pragma unroll
            for (int j = 0; j < 4; j++) {
                int q = (int)((v >> (8 * j)) & 255u);
                if (q <= qt) {
                    int pos = atomicAdd(CCNT, 1);
                    if (pos < 1024) CLIST[pos] = (uint32_t)((row << 8) | ((w0 + w) * 4 + j));
                }
            }
        }
    }
    __syncthreads();

    // ---- rescore candidates with the bit-exact R1 formula ----
    {
        int total = min(CCNT[0], 1024) * 8;
        for (int t = tid; t < total; t += TPB) {
            uint32_t e = CLIST[t >> 3];
            int row = (int)(e >> 8);
            int code = ((int)(e & 255u)) * 8 + (t & 7);
            const float4* xr = (const float4*)(x + (size_t)(base_row + row) * DIMK);
            const float4* er = (const float4*)(g_embT + code * DIMK);
            float aL[4] = {0, 0, 0, 0}, aH[4] = {0, 0, 0, 0};
#pragma unroll
            for (int t8 = 0; t8 < 8; t8++) {
                float4 xv0 = xr[2 * t8], xv1 = xr[2 * t8 + 1];
                float4 ev0 = er[2 * t8], ev1 = er[2 * t8 + 1];
                aL[0] = fmaf(-2.f * xv0.x, ev0.x, aL[0]); aH[0] = fmaf(-2.f * xv0.y, ev0.y, aH[0]);
                aL[1] = fmaf(-2.f * xv0.z, ev0.z, aL[1]); aH[1] = fmaf(-2.f * xv0.w, ev0.w, aH[1]);
                aL[2] = fmaf(-2.f * xv1.x, ev1.x, aL[2]); aH[2] = fmaf(-2.f * xv1.y, ev1.y, aH[2]);
                aL[3] = fmaf(-2.f * xv1.z, ev1.z, aL[3]); aH[3] = fmaf(-2.f * xv1.w, ev1.w, aH[3]);
            }
            float dot = ((aL[0] + aH[0]) + (aL[1] + aH[1])) + ((aL[2] + aH[2]) + (aL[3] + aH[3]));
            float s = nsm[code] + dot;
            ull key = (((ull)fkey(s)) << 32) | (uint32_t)code;
            atomicMin(&ROWBEST[row], key);
        }
    }
    __syncthreads();
    for (int i = tid; i < 128; i += TPB) WIN[i] = (int)(ROWBEST[i] & 0xFFFFFFFFull);
    __syncthreads();

    // ---- phase 2: quantize writes + diff + ind (16 rows per warp) ----
    float dsum = 0.f;
    bool write_ind = (out_size >= NTOT + 1 + NROWS);
#pragma unroll 1
    for (int i = 0; i < 16; i++) {
        int r = wid * 16 + i;
        int bk = WIN[r];
        size_t n = (size_t)base_row + r;
        float2 ev = ((const float2*)(g_embT + bk * DIMK))[lane];
        float2 xv = ((const float2*)(x + n * DIMK))[lane];
        ((float2*)(out + n * DIMK))[lane] = ev;
        float dx = ev.x - xv.x, dy = ev.y - xv.y;
        dsum = fmaf(dx, dx, dsum);
        dsum = fmaf(dy, dy, dsum);
        if (lane == 0 && write_ind) out[NTOT + 1 + n] = (float)bk;
    }

    red[tid] = dsum;
    __syncthreads();
#pragma unroll
    for (int s = TPB / 2; s > 0; s >>= 1) {
        if (tid < s) red[tid] += red[tid + s];
        __syncthreads();
    }
    if (tid == 0) {
        unsigned long long q2 = (unsigned long long)((double)red[0] * 1048576.0 + 0.5);
        atomicAdd(&g_diff_acc, q2);
        __threadfence();
        unsigned t = atomicAdd(&g_ticket, 1u);
        if (t == (unsigned)(NBLK - 1)) {
            unsigned long long tot = atomicExch(&g_diff_acc, 0ull);
            atomicExch(&g_ticket, 0u);
            if (out_size >= NTOT + 1)
                out[NTOT] = (float)((double)tot * (1.0 / 1048576.0) / (double)NTOT);
        }
    }
}

extern "C" void kernel_launch(void* const* d_in, const int* in_sizes, int n_in,
                              void* d_out, int out_size) {
    const float* x = (const float*)d_in[0];
    const float* embed = (const float*)d_in[1];
    float* out = (float*)d_out;

    cudaFuncSetAttribute(vq_mma_kernel,
                         cudaFuncAttributeMaxDynamicSharedMemorySize, SM_BYTES);

    vq_prep<<<64, 256>>>(embed);
    vq_mma_kernel<<<NBLK, TPB, SM_BYTES>>>(x, out, out_size);
}

// round 15
// speedup vs baseline: 1.7191x; 1.7191x over previous
#include <cuda_runtime.h>
#include <cstdint>

// VQ quantize: hh-only tf32 MMA prefilter + uncapped per-warp candidate
// rescore (bit-exact R1/R14 scalar formula -> exact argmin, proven twice).
// fp32 block-mins (no quantization slop) => ~1-2 flagged blocks per row.
// x: [131072, 64] f32, embed: [64, 512] f32.
// Out f32: quantize (8388608) | diff (1) | embed_ind (131072).

#define DIMK 64
#define NCODE 512
#define NROWS (32 * 64 * 64)
#define NTOT (NROWS * DIMK)
#define TPB 256
#define M_TILE 128
#define NBLK (NROWS / M_TILE)   // 1024

// smem layout (bytes)
#define SM_BH0 0                 // 16384  (8 nc-blocks of hh B fragments)
#define SM_BH1 16384             // 16384
#define SM_NRM 32768             // 2048   float[512]
#define SM_BLKMIN 34816          // 32768  float[128][64]
#define SM_THR 67584             // 512    float[128]
#define SM_WIN 68096             // 512    int[128]
#define SM_RED 68608             // 1024   float[256]
#define SM_BYTES 69632           // 3 CTAs/SM: 3*69632 = 204KB < 227KB

typedef unsigned long long ull;

__device__ __align__(16) float2 g_Bh[64 * 8 * 32];     // [nc][kc][lane] = {bh0,bh1}
__device__ __align__(16) float g_embT[NCODE * DIMK];   // fp32 codes [k][d]
__device__ float g_nrm[NCODE];
__device__ float g_maxE2;                              // max ||e||^2 (monotone atomicMax)
__device__ unsigned long long g_diff_acc;
__device__ unsigned int g_ticket;

__device__ __forceinline__ uint32_t smem_u32(const void* p) {
    uint32_t a;
    asm("{ .reg .u64 t; cvta.to.shared.u64 t, %1; cvt.u32.u64 %0, t; }" : "=r"(a) : "l"(p));
    return a;
}
__device__ __forceinline__ uint32_t tf32_hi(float f) {
    uint32_t r;
    asm("cvt.rna.tf32.f32 %0, %1;" : "=r"(r) : "f"(f));
    return r;
}
__device__ __forceinline__ void mma8(float* c, const uint32_t* a, uint32_t b0, uint32_t b1) {
    asm("mma.sync.aligned.m16n8k8.row.col.f32.tf32.tf32.f32 "
        "{%0,%1,%2,%3}, {%4,%5,%6,%7}, {%8,%9}, {%0,%1,%2,%3};"
        : "+f"(c[0]), "+f"(c[1]), "+f"(c[2]), "+f"(c[3])
        : "r"(a[0]), "r"(a[1]), "r"(a[2]), "r"(a[3]), "r"(b0), "r"(b1));
}
__device__ __forceinline__ void cp16(uint32_t s, const void* g) {
    asm volatile("cp.async.cg.shared.global [%0], [%1], 16;" :: "r"(s), "l"(g) : "memory");
}
#define CP_COMMIT() asm volatile("cp.async.commit_group;" ::: "memory")
#define CP_WAIT1()  asm volatile("cp.async.wait_group 1;" ::: "memory")
#define CP_WAIT0()  asm volatile("cp.async.wait_group 0;" ::: "memory")

__device__ __forceinline__ uint32_t fkey(float f) {
    uint32_t b = __float_as_uint(f);
    return (b & 0x80000000u) ? ~b : (b | 0x80000000u);
}

// ---- prep: codebook transpose, norms, maxE^2, hh B fragments ----
__global__ void vq_prep(const float* __restrict__ embed) {
    int gtid = blockIdx.x * blockDim.x + threadIdx.x;   // 16384

    if (gtid < NCODE) {
        int t = gtid;
        float nr = 0.f;
        for (int d = 0; d < DIMK; d++) {
            float e = embed[d * NCODE + t];
            g_embT[t * DIMK + d] = e;
            nr = fmaf(e, e, nr);
        }
        g_nrm[t] = nr;
        atomicMax((int*)&g_maxE2, __float_as_int(nr));  // nr>=0: int-bit monotone
    }

    int i = gtid;   // [nc][kc][lane]
    int lane = i & 31;
    int kc = (i >> 5) & 7;
    int nc = i >> 8;
    int gid = lane >> 2, tig = lane & 3;
    int n = nc * 8 + gid;
    int k0 = kc * 8 + tig;
    float v0 = -2.f * embed[k0 * NCODE + n];
    float v1 = -2.f * embed[(k0 + 4) * NCODE + n];
    float2 f;
    f.x = __uint_as_float(tf32_hi(v0));
    f.y = __uint_as_float(tf32_hi(v1));
    g_Bh[i] = f;
}

__global__ __launch_bounds__(TPB, 3)
void vq_mma_kernel(const float* __restrict__ x,
                   float* __restrict__ out,
                   int out_size) {
    extern __shared__ char smem[];
    float* nsm = (float*)(smem + SM_NRM);
    float* BLKMIN = (float*)(smem + SM_BLKMIN);
    float* THR = (float*)(smem + SM_THR);
    int* WIN = (int*)(smem + SM_WIN);
    float* red = (float*)(smem + SM_RED);

    int tid = threadIdx.x, wid = tid >> 5, lane = tid & 31;
    int gid = lane >> 2, tig = lane & 3;
    int base_row = blockIdx.x * M_TILE;
    const uint32_t FULL = 0xffffffffu;

    // async load of Bh chunk 0 (16KB = 1024 uint4)
    {
        uint32_t dst = smem_u32(smem + SM_BH0) + tid * 16;
        const uint4* src = ((const uint4*)g_Bh) + tid;
#pragma unroll
        for (int i = 0; i < 1024 / TPB; i++)
            cp16(dst + i * TPB * 16, src + i * TPB);
        CP_COMMIT();
    }

    for (int i = tid; i < NCODE; i += TPB) nsm[i] = g_nrm[i];

    // A fragments (tf32 hi only) + per-row ||x||^2 partials
    int m0 = wid * 16;
    uint32_t Ah[8][4];
    float nx0 = 0.f, nx1 = 0.f;
    {
        const float* xr0 = x + (size_t)(base_row + m0 + gid) * DIMK;
        const float* xr8 = xr0 + 8 * DIMK;
#pragma unroll
        for (int kc = 0; kc < 8; kc++) {
            int c0 = kc * 8 + tig;
            float f0 = __ldg(xr0 + c0);
            float f1 = __ldg(xr8 + c0);
            float f2 = __ldg(xr0 + c0 + 4);
            float f3 = __ldg(xr8 + c0 + 4);
            Ah[kc][0] = tf32_hi(f0);
            Ah[kc][1] = tf32_hi(f1);
            Ah[kc][2] = tf32_hi(f2);
            Ah[kc][3] = tf32_hi(f3);
            nx0 = fmaf(f0, f0, nx0); nx0 = fmaf(f2, f2, nx0);
            nx1 = fmaf(f1, f1, nx1); nx1 = fmaf(f3, f3, nx1);
        }
    }
    nx0 += __shfl_xor_sync(FULL, nx0, 1); nx0 += __shfl_xor_sync(FULL, nx0, 2);
    nx1 += __shfl_xor_sync(FULL, nx1, 1); nx1 += __shfl_xor_sync(FULL, nx1, 2);

    float best0 = __int_as_float(0x7f800000), best1 = best0;

    // ---- pass 1: hh-only MMA over 8 chunks x 8 blocks, fp32 block mins ----
#pragma unroll 1
    for (int c = 0; c < 8; c++) {
        if (c < 7) {
            uint32_t dst = smem_u32(smem + ((c & 1) ? SM_BH0 : SM_BH1)) + tid * 16;
            const uint4* src = ((const uint4*)g_Bh) + (c + 1) * 1024 + tid;
#pragma unroll
            for (int i = 0; i < 1024 / TPB; i++)
                cp16(dst + i * TPB * 16, src + i * TPB);
            CP_COMMIT();
            CP_WAIT1();
        } else {
            CP_WAIT0();
        }
        __syncthreads();

        const float2* Bq = (const float2*)(smem + ((c & 1) ? SM_BH1 : SM_BH0));

#pragma unroll 2
        for (int ncl = 0; ncl < 8; ncl++) {
            float2 b[8];
#pragma unroll
            for (int kc = 0; kc < 8; kc++) b[kc] = Bq[(ncl * 8 + kc) * 32 + lane];

            float hh[4] = {0, 0, 0, 0};
#pragma unroll
            for (int kc = 0; kc < 8; kc++)
                mma8(hh, Ah[kc], __float_as_uint(b[kc].x), __float_as_uint(b[kc].y));

            int blk = c * 8 + ncl;
            float2 nv = *(const float2*)(nsm + blk * 8 + 2 * tig);
            float bm0 = fminf(hh[0] + nv.x, hh[1] + nv.y);
            float bm1 = fminf(hh[2] + nv.x, hh[3] + nv.y);
            best0 = fminf(best0, bm0);
            best1 = fminf(best1, bm1);
            bm0 = fminf(bm0, __shfl_xor_sync(FULL, bm0, 1));
            bm0 = fminf(bm0, __shfl_xor_sync(FULL, bm0, 2));
            bm1 = fminf(bm1, __shfl_xor_sync(FULL, bm1, 1));
            bm1 = fminf(bm1, __shfl_xor_sync(FULL, bm1, 2));
            if (tig == 0) {
                BLKMIN[(m0 + gid) * 64 + blk] = bm0;
                BLKMIN[(m0 + gid + 8) * 64 + blk] = bm1;
            }
        }
        __syncthreads();
    }

    // ---- row thresholds: best + 2*(2^-8*||x||*maxE + 0.05) ----
    best0 = fminf(best0, __shfl_xor_sync(FULL, best0, 1));
    best0 = fminf(best0, __shfl_xor_sync(FULL, best0, 2));
    best1 = fminf(best1, __shfl_xor_sync(FULL, best1, 1));
    best1 = fminf(best1, __shfl_xor_sync(FULL, best1, 2));
    {
        float maxE = sqrtf(__ldg(&g_maxE2));
        if (tig == 0) {
            float B0 = 0.00390625f * sqrtf(nx0) * maxE + 0.05f;
            float B1 = 0.00390625f * sqrtf(nx1) * maxE + 0.05f;
            THR[m0 + gid] = best0 + 2.f * B0;
            THR[m0 + gid + 8] = best1 + 2.f * B1;
        }
    }
    __syncthreads();

    // ---- per-warp scan + rescore (uncapped; bit-exact R1/R14 formula) ----
#pragma unroll 1
    for (int i = 0; i < 16; i++) {
        int row = wid * 16 + i;
        float thr = THR[row];
        const float* bm = BLKMIN + row * 64;
        float mv0 = bm[lane], mv1 = bm[lane + 32];
        uint32_t f0 = __ballot_sync(FULL, mv0 <= thr);
        uint32_t f1 = __ballot_sync(FULL, mv1 <= thr);
        ull bestk = ~0ull;
        const float4* xr = (const float4*)(x + (size_t)(base_row + row) * DIMK);
#pragma unroll 1
        for (int half = 0; half < 2; half++) {
            uint32_t m = half ? f1 : f0;
            while (m) {
                int b = __ffs(m) - 1;
                m &= m - 1;
                int blk = half * 32 + b;
                if (lane < 8) {
                    int code = blk * 8 + lane;
                    const float4* er = (const float4*)(g_embT + code * DIMK);
                    float aL[4] = {0, 0, 0, 0}, aH[4] = {0, 0, 0, 0};
#pragma unroll
                    for (int t8 = 0; t8 < 8; t8++) {
                        float4 xv0 = xr[2 * t8], xv1 = xr[2 * t8 + 1];
                        float4 ev0 = er[2 * t8], ev1 = er[2 * t8 + 1];
                        aL[0] = fmaf(-2.f * xv0.x, ev0.x, aL[0]); aH[0] = fmaf(-2.f * xv0.y, ev0.y, aH[0]);
                        aL[1] = fmaf(-2.f * xv0.z, ev0.z, aL[1]); aH[1] = fmaf(-2.f * xv0.w, ev0.w, aH[1]);
                        aL[2] = fmaf(-2.f * xv1.x, ev1.x, aL[2]); aH[2] = fmaf(-2.f * xv1.y, ev1.y, aH[2]);
                        aL[3] = fmaf(-2.f * xv1.z, ev1.z, aL[3]); aH[3] = fmaf(-2.f * xv1.w, ev1.w, aH[3]);
                    }
                    float dot = ((aL[0] + aH[0]) + (aL[1] + aH[1])) + ((aL[2] + aH[2]) + (aL[3] + aH[3]));
                    float s = nsm[code] + dot;
                    ull key = (((ull)fkey(s)) << 32) | (uint32_t)code;
                    bestk = min(bestk, key);
                }
            }
        }
#pragma unroll
        for (int o = 16; o > 0; o >>= 1) {
            ull ok = __shfl_xor_sync(FULL, bestk, o);
            bestk = min(bestk, ok);
        }
        if (lane == 0) WIN[row] = (int)(bestk & 0xFFFFFFFFull);
    }
    __syncthreads();

    // ---- phase 2: quantize writes + diff + ind (16 rows per warp) ----
    float dsum = 0.f;
    bool write_ind = (out_size >= NTOT + 1 + NROWS);
#pragma unroll 1
    for (int i = 0; i < 16; i++) {
        int r = wid * 16 + i;
        int bk = WIN[r];
        size_t n = (size_t)base_row + r;
        float2 ev = ((const float2*)(g_embT + bk * DIMK))[lane];
        float2 xv = ((const float2*)(x + n * DIMK))[lane];
        ((float2*)(out + n * DIMK))[lane] = ev;
        float dx = ev.x - xv.x, dy = ev.y - xv.y;
        dsum = fmaf(dx, dx, dsum);
        dsum = fmaf(dy, dy, dsum);
        if (lane == 0 && write_ind) out[NTOT + 1 + n] = (float)bk;
    }

    red[tid] = dsum;
    __syncthreads();
#pragma unroll
    for (int s = TPB / 2; s > 0; s >>= 1) {
        if (tid < s) red[tid] += red[tid + s];
        __syncthreads();
    }
    if (tid == 0) {
        unsigned long long q2 = (unsigned long long)((double)red[0] * 1048576.0 + 0.5);
        atomicAdd(&g_diff_acc, q2);
        __threadfence();
        unsigned t = atomicAdd(&g_ticket, 1u);
        if (t == (unsigned)(NBLK - 1)) {
            unsigned long long tot = atomicExch(&g_diff_acc, 0ull);
            atomicExch(&g_ticket, 0u);
            if (out_size >= NTOT + 1)
                out[NTOT] = (float)((double)tot * (1.0 / 1048576.0) / (double)NTOT);
        }
    }
}

extern "C" void kernel_launch(void* const* d_in, const int* in_sizes, int n_in,
                              void* d_out, int out_size) {
    const float* x = (const float*)d_in[0];
    const float* embed = (const float*)d_in[1];
    float* out = (float*)d_out;

    cudaFuncSetAttribute(vq_mma_kernel,
                         cudaFuncAttributeMaxDynamicSharedMemorySize, SM_BYTES);

    vq_prep<<<64, 256>>>(embed);
    vq_mma_kernel<<<NBLK, TPB, SM_BYTES>>>(x, out, out_size);
}